// round 14
// baseline (speedup 1.0000x reference)
#include <cuda_runtime.h>
#include <cstdint>

// ConditionalCNF via warp-level mma.sync (m16n8k16 f16, f32 accum).
// R14: R13 proved the kernel is latency-bound (no pipe >40%, issue 68%,
// MUFU cut was neutral). Halve the warp tile to 16 samples (acc regs 64->32)
// to reach 6 CTAs/SM and 6 warps/SMSP. Per-sample math identical to R13.
//
//   lane: q = lane>>2, c4 = lane&3
//   sample rows per thread: {q, q+8}
//   layer-1 k-units per thread: u0 = 16kt+8e+2c4, u0+1  (kt,e in {0,1})
//   D cols per thread: {2c4, 2c4+1} + 8nt

using u32 = unsigned int;

static constexpr int NSTEPS = 20;
static constexpr int BLK = 128;

__device__ __forceinline__ u32 cvt_f16x2(float hi, float lo) {
    u32 d; asm("cvt.rn.f16x2.f32 %0, %1, %2;" : "=r"(d) : "f"(hi), "f"(lo));
    return d;
}
__device__ __forceinline__ u32 tanh_h2(u32 x) {
    u32 d; asm("tanh.approx.f16x2 %0, %1;" : "=r"(d) : "r"(x)); return d;
}
__device__ __forceinline__ void h2_to_f32(u32 h2, float& lo, float& hi) {
    asm("{\n\t.reg .f16 l, h;\n\tmov.b32 {l, h}, %2;\n\t"
        "cvt.f32.f16 %0, l;\n\tcvt.f32.f16 %1, h;\n\t}"
        : "=f"(lo), "=f"(hi) : "r"(h2));
}
__device__ __forceinline__ u32 hmul2o(u32 a, u32 b) {
    u32 d; asm("mul.rn.f16x2 %0, %1, %2;" : "=r"(d) : "r"(a), "r"(b));
    return d;
}
__device__ __forceinline__ u32 hfma2o(u32 a, u32 b, u32 c) {
    u32 d; asm("fma.rn.f16x2 %0, %1, %2, %3;" : "=r"(d) : "r"(a), "r"(b), "r"(c));
    return d;
}
__device__ __forceinline__ void mma_f16_acc(float& c0, float& c1, float& c2, float& c3,
                                            u32 a0, u32 a1, u32 a2, u32 a3,
                                            u32 b0, u32 b1) {
    asm volatile("mma.sync.aligned.m16n8k16.row.col.f32.f16.f16.f32 "
                 "{%0,%1,%2,%3}, {%4,%5,%6,%7}, {%8,%9}, {%0,%1,%2,%3};"
                 : "+f"(c0), "+f"(c1), "+f"(c2), "+f"(c3)
                 : "r"(a0), "r"(a1), "r"(a2), "r"(a3), "r"(b0), "r"(b1));
}
__device__ __forceinline__ void mma_f16_init(float& d0, float& d1, float& d2, float& d3,
                                             u32 a0, u32 a1, u32 a2, u32 a3,
                                             u32 b0, u32 b1, float cl, float ch) {
    asm volatile("mma.sync.aligned.m16n8k16.row.col.f32.f16.f16.f32 "
                 "{%0,%1,%2,%3}, {%4,%5,%6,%7}, {%8,%9}, {%10,%11,%10,%11};"
                 : "=f"(d0), "=f"(d1), "=f"(d2), "=f"(d3)
                 : "r"(a0), "r"(a1), "r"(a2), "r"(a3), "r"(b0), "r"(b1),
                   "f"(cl), "f"(ch));
}

__global__ void __launch_bounds__(BLK, 6)
cnf_kernel(const float* __restrict__ T,
           const float* __restrict__ cond,
           const float* __restrict__ gW1,
           const float* __restrict__ gb1,
           const float* __restrict__ gW2,
           const float* __restrict__ gb2,
           const float* __restrict__ gW3,
           const float* __restrict__ gb3,
           float* __restrict__ out,
           int B)
{
    __shared__ float2 spre1[8 * BLK];   // layer1 preact pairs [slot][tid] (8 KB)
    __shared__ uint2  sB   [8 * 32];    // W2 f16x2 B-frags [tile][lane]   (2 KB)
    __shared__ float2 swf  [16];        // w10 f32 pairs   [kp*4+c4]
    __shared__ u32    sw16 [16];        // w10 f16x2
    __shared__ u32    snw16[16];        // -w10 f16x2
    __shared__ float2 sb2  [16];        // {b2[n0], b2[n0+1]} per (nt,c4)
    __shared__ float2 sw3  [16];        // {w3[n0], w3[n0+1]}

    const int tid = threadIdx.x;
    const int ln  = tid & 31;
    const int wid = tid >> 5;
    const int q   = ln >> 2;
    const int c4  = ln & 3;

    // ---- one-time smem init ----
    for (int e = tid; e < 8 * 32; e += BLK) {
        int t = e >> 5, l = e & 31;
        int kt = t >> 2, nt = t & 3;
        int n  = (l >> 2) + 8 * nt;
        int k0 = 16 * kt + 2 * (l & 3);
        const float* r = gW2 + n * 32 + k0;
        sB[e] = make_uint2(cvt_f16x2(r[1], r[0]), cvt_f16x2(r[9], r[8]));
    }
    if (tid < 16) {
        int kp = tid >> 2, cc = tid & 3;     // kp = 2*kt + e
        int kt = kp >> 1, ee = kp & 1;
        int u0 = 16 * kt + 8 * ee + 2 * cc;
        float w0 = gW1[u0 * 9], w1 = gW1[(u0 + 1) * 9];
        swf[tid]   = make_float2(w0, w1);
        sw16[tid]  = cvt_f16x2(w1, w0);
        snw16[tid] = cvt_f16x2(-w1, -w0);
        int nt = tid >> 2;
        int n0 = 2 * cc + 8 * nt;
        sb2[tid] = make_float2(gb2[n0], gb2[n0 + 1]);
        sw3[tid] = make_float2(gW3[n0], gW3[n0 + 1]);
    }

    // ---- per-thread setup: RK state + pre1 into smem ----
    const int gwbase = blockIdx.x * 64 + wid * 16;   // 16 samples per warp
    float z[2], logp[2];
#pragma unroll
    for (int rs = 0; rs < 2; rs++) {
        int s = gwbase + q + 8 * rs;
        z[rs] = __ldg(T + s);
        logp[rs] = 0.0f;
        const float4* cp = reinterpret_cast<const float4*>(cond) + s * 2;
        float4 ca = __ldg(cp), cb = __ldg(cp + 1);
        float cc[8] = {ca.x, ca.y, ca.z, ca.w, cb.x, cb.y, cb.z, cb.w};
#pragma unroll
        for (int kp = 0; kp < 4; kp++) {
            int kt = kp >> 1, ee = kp & 1;
            int u0 = 16 * kt + 8 * ee + 2 * c4;
            int u1 = u0 + 1;
            float p0 = __ldg(gb1 + u0), p1 = __ldg(gb1 + u1);
#pragma unroll
            for (int c = 0; c < 8; c++) {
                p0 = fmaf(cc[c], __ldg(gW1 + u0 * 9 + 1 + c), p0);
                p1 = fmaf(cc[c], __ldg(gW1 + u1 * 9 + 1 + c), p1);
            }
            spre1[(rs * 4 + kp) * BLK + tid] = make_float2(p0, p1);
        }
    }
    const float b3v = __ldg(gb3);
    __syncthreads();

    const float dt  = 1.0f / (float)NSTEPS;
    const float dt6 = dt / 6.0f;

#pragma unroll 1
    for (int step = 0; step < NSTEPS; step++) {
        float zs[2], az[2], ad2[2];
#pragma unroll
        for (int rs = 0; rs < 2; rs++) { zs[rs] = z[rs]; az[rs] = 0.0f; ad2[rs] = 0.0f; }

#pragma unroll 1
        for (int st = 0; st < 4; st++) {
            float accS[16], accT[16];

            // ---- fused layer1 (f16x2 tanh) + dual f16 matvec over kt ----
#pragma unroll
            for (int kt = 0; kt < 2; kt++) {
                u32 hA[2][2], gA[2][2];   // [rs][e]
#pragma unroll
                for (int ee = 0; ee < 2; ee++) {
                    int kp = 2 * kt + ee;
                    int idx = kp * 4 + c4;
                    float2 wv = swf[idx];
                    u32 w16 = sw16[idx], nw16 = snw16[idx];
#pragma unroll
                    for (int rs = 0; rs < 2; rs++) {
                        float2 pr = spre1[(rs * 4 + kp) * BLK + tid];
                        float x0 = fmaf(zs[rs], wv.x, pr.x);
                        float x1 = fmaf(zs[rs], wv.y, pr.y);
                        u32 h = tanh_h2(cvt_f16x2(x1, x0));
                        u32 hh = hmul2o(h, h);
                        hA[rs][ee] = h;
                        gA[rs][ee] = hfma2o(hh, nw16, w16);  // (1-h^2)*w10
                    }
                }
#pragma unroll
                for (int nt = 0; nt < 4; nt++) {
                    uint2 bb = sB[(kt * 4 + nt) * 32 + ln];
                    int ba = nt * 4;
                    if (kt == 0) {
                        float2 bv = sb2[nt * 4 + c4];
                        mma_f16_init(accS[ba], accS[ba+1], accS[ba+2], accS[ba+3],
                                     hA[0][0], hA[1][0], hA[0][1], hA[1][1],
                                     bb.x, bb.y, bv.x, bv.y);
                        mma_f16_init(accT[ba], accT[ba+1], accT[ba+2], accT[ba+3],
                                     gA[0][0], gA[1][0], gA[0][1], gA[1][1],
                                     bb.x, bb.y, 0.0f, 0.0f);
                    } else {
                        mma_f16_acc(accS[ba], accS[ba+1], accS[ba+2], accS[ba+3],
                                    hA[0][0], hA[1][0], hA[0][1], hA[1][1],
                                    bb.x, bb.y);
                        mma_f16_acc(accT[ba], accT[ba+1], accT[ba+2], accT[ba+3],
                                    gA[0][0], gA[1][0], gA[0][1], gA[1][1],
                                    bb.x, bb.y);
                    }
                }
            }

            // ---- merged epilogue: f16x2 tanh on accS pairs ----
            float dzp[2] = {0.f, 0.f};
            float dvp[2] = {0.f, 0.f};
#pragma unroll
            for (int nt = 0; nt < 4; nt++) {
                float2 wv = sw3[nt * 4 + c4];
                int ba = nt * 4;
#pragma unroll
                for (int rs = 0; rs < 2; rs++) {
                    u32 hp = tanh_h2(cvt_f16x2(accS[ba + 2*rs + 1], accS[ba + 2*rs]));
                    float h0, h1; h2_to_f32(hp, h0, h1);
                    dzp[rs] = fmaf(wv.x, h0, dzp[rs]);
                    dzp[rs] = fmaf(wv.y, h1, dzp[rs]);
                    float g0 = fmaf(-h0, h0, 1.0f) * wv.x;
                    float g1 = fmaf(-h1, h1, 1.0f) * wv.y;
                    dvp[rs] = fmaf(g0, accT[ba + 2*rs], dvp[rs]);
                    dvp[rs] = fmaf(g1, accT[ba + 2*rs + 1], dvp[rs]);
                }
            }

            // ---- quad reduction + RK accumulate ----
            const float coef = (st == 1 || st == 2) ? 2.0f : 1.0f;
            const float a = (st == 2) ? dt : (0.5f * dt);
#pragma unroll
            for (int rs = 0; rs < 2; rs++) {
                float dz = dzp[rs], dv = dvp[rs];
                dz += __shfl_xor_sync(0xffffffffu, dz, 1);
                dz += __shfl_xor_sync(0xffffffffu, dz, 2);
                dv += __shfl_xor_sync(0xffffffffu, dv, 1);
                dv += __shfl_xor_sync(0xffffffffu, dv, 2);
                float kz = dz + b3v;
                az[rs]  = fmaf(coef, kz, az[rs]);
                ad2[rs] = fmaf(coef, dv, ad2[rs]);
                zs[rs]  = fmaf(a, kz, z[rs]);
            }
        }

#pragma unroll
        for (int rs = 0; rs < 2; rs++) {
            z[rs]    = fmaf(dt6, az[rs],  z[rs]);
            logp[rs] = fmaf(dt6, ad2[rs], logp[rs]);
        }
    }

    if (c4 == 0) {
#pragma unroll
        for (int rs = 0; rs < 2; rs++) {
            int s = gwbase + q + 8 * rs;
            out[s]     = z[rs];
            out[B + s] = logp[rs];
        }
    }
}

extern "C" void kernel_launch(void* const* d_in, const int* in_sizes, int n_in,
                              void* d_out, int out_size) {
    const float* T    = (const float*)d_in[0];
    const float* cond = (const float*)d_in[1];
    const float* W1   = (const float*)d_in[2];
    const float* b1   = (const float*)d_in[3];
    const float* W2   = (const float*)d_in[4];
    const float* b2   = (const float*)d_in[5];
    const float* W3   = (const float*)d_in[6];
    const float* b3   = (const float*)d_in[7];
    float* out = (float*)d_out;

    const int B = in_sizes[0];
    const int blocks = (B + 63) / 64;   // 64 samples per CTA (16 per warp)
    cnf_kernel<<<blocks, BLK>>>(T, cond, W1, b1, W2, b2, W3, b3, out, B);
}

// round 15
// speedup vs baseline: 1.0456x; 1.0456x over previous
#include <cuda_runtime.h>
#include <cstdint>

// ConditionalCNF via warp-level mma.sync (m16n8k16 f16, f32 accum).
// R15: 32 samples/warp (R12/13 config, proven best). Epilogue dot-products
// (dz = w3.h2, dv = w3.(1-h2^2)t) moved onto the tensor pipe: tanh.f16x2
// outputs of accS pairs ARE m16n8k16 A-fragments; B = w3 replicated over n.
// The MMA also performs the cross-lane k-reduction -> all 16 SHFLs gone;
// b3 folded into the MMA c-operand. u = t - h^2 t built packed in f16.
//
//   lane: q = lane>>2, c4 = lane&3
//   sample rows per thread: {q+8rs, rs=0..3}
//   layer-1 k-units per thread: u0 = 16kt+8e+2c4, u0+1  (kt,e in {0,1})
//   D cols per thread: {2c4, 2c4+1} + 8nt

using u32 = unsigned int;

static constexpr int NSTEPS = 20;
static constexpr int BLK = 128;

__device__ __forceinline__ u32 cvt_f16x2(float hi, float lo) {
    u32 d; asm("cvt.rn.f16x2.f32 %0, %1, %2;" : "=r"(d) : "f"(hi), "f"(lo));
    return d;
}
__device__ __forceinline__ u32 tanh_h2(u32 x) {
    u32 d; asm("tanh.approx.f16x2 %0, %1;" : "=r"(d) : "r"(x)); return d;
}
__device__ __forceinline__ u32 hmul2o(u32 a, u32 b) {
    u32 d; asm("mul.rn.f16x2 %0, %1, %2;" : "=r"(d) : "r"(a), "r"(b));
    return d;
}
__device__ __forceinline__ u32 hsub2o(u32 a, u32 b) {
    u32 d; asm("sub.rn.f16x2 %0, %1, %2;" : "=r"(d) : "r"(a), "r"(b));
    return d;
}
__device__ __forceinline__ u32 hfma2o(u32 a, u32 b, u32 c) {
    u32 d; asm("fma.rn.f16x2 %0, %1, %2, %3;" : "=r"(d) : "r"(a), "r"(b), "r"(c));
    return d;
}
__device__ __forceinline__ void mma_f16_acc(float& c0, float& c1, float& c2, float& c3,
                                            u32 a0, u32 a1, u32 a2, u32 a3,
                                            u32 b0, u32 b1) {
    asm volatile("mma.sync.aligned.m16n8k16.row.col.f32.f16.f16.f32 "
                 "{%0,%1,%2,%3}, {%4,%5,%6,%7}, {%8,%9}, {%0,%1,%2,%3};"
                 : "+f"(c0), "+f"(c1), "+f"(c2), "+f"(c3)
                 : "r"(a0), "r"(a1), "r"(a2), "r"(a3), "r"(b0), "r"(b1));
}
__device__ __forceinline__ void mma_f16_init(float& d0, float& d1, float& d2, float& d3,
                                             u32 a0, u32 a1, u32 a2, u32 a3,
                                             u32 b0, u32 b1, float cl, float ch) {
    asm volatile("mma.sync.aligned.m16n8k16.row.col.f32.f16.f16.f32 "
                 "{%0,%1,%2,%3}, {%4,%5,%6,%7}, {%8,%9}, {%10,%11,%10,%11};"
                 : "=f"(d0), "=f"(d1), "=f"(d2), "=f"(d3)
                 : "r"(a0), "r"(a1), "r"(a2), "r"(a3), "r"(b0), "r"(b1),
                   "f"(cl), "f"(ch));
}

__global__ void __launch_bounds__(BLK, 4)
cnf_kernel(const float* __restrict__ T,
           const float* __restrict__ cond,
           const float* __restrict__ gW1,
           const float* __restrict__ gb1,
           const float* __restrict__ gW2,
           const float* __restrict__ gb2,
           const float* __restrict__ gW3,
           const float* __restrict__ gb3,
           float* __restrict__ out,
           int B)
{
    __shared__ float2 spre1[16 * BLK];  // layer1 preact pairs [slot][tid] (16 KB)
    __shared__ uint2  sB   [8 * 32];    // W2 f16x2 B-frags [tile][lane]    (2 KB)
    __shared__ float2 swf  [16];        // w10 f32 pairs   [kp*4+c4]
    __shared__ u32    sw16 [16];        // w10 f16x2
    __shared__ u32    snw16[16];        // -w10 f16x2
    __shared__ float2 sb2  [16];        // {b2[n0], b2[n0+1]} per (nt,c4)

    const int tid = threadIdx.x;
    const int ln  = tid & 31;
    const int wid = tid >> 5;
    const int q   = ln >> 2;
    const int c4  = ln & 3;

    // ---- one-time smem init ----
    for (int e = tid; e < 8 * 32; e += BLK) {
        int t = e >> 5, l = e & 31;
        int kt = t >> 2, nt = t & 3;
        int n  = (l >> 2) + 8 * nt;
        int k0 = 16 * kt + 2 * (l & 3);
        const float* r = gW2 + n * 32 + k0;
        sB[e] = make_uint2(cvt_f16x2(r[1], r[0]), cvt_f16x2(r[9], r[8]));
    }
    if (tid < 16) {
        int kp = tid >> 2, cc = tid & 3;     // kp = 2*kt + e
        int kt = kp >> 1, ee = kp & 1;
        int u0 = 16 * kt + 8 * ee + 2 * cc;
        float w0 = gW1[u0 * 9], w1 = gW1[(u0 + 1) * 9];
        swf[tid]   = make_float2(w0, w1);
        sw16[tid]  = cvt_f16x2(w1, w0);
        snw16[tid] = cvt_f16x2(-w1, -w0);
        int nt = tid >> 2;
        int n0 = 2 * cc + 8 * nt;
        sb2[tid] = make_float2(gb2[n0], gb2[n0 + 1]);
    }

    // w3 B-fragments for the epilogue MMAs (replicated over n; per-thread regs)
    // kh selects k-halves 0..15 / 16..31 of the n-unit axis.
    u32 w3b0[2], w3b1[2];
#pragma unroll
    for (int kh = 0; kh < 2; kh++) {
        int k0 = 16 * kh + 2 * c4;
        w3b0[kh] = cvt_f16x2(__ldg(gW3 + k0 + 1), __ldg(gW3 + k0));
        w3b1[kh] = cvt_f16x2(__ldg(gW3 + k0 + 9), __ldg(gW3 + k0 + 8));
    }

    // ---- per-thread setup: RK state + pre1 into smem ----
    const int gwbase = blockIdx.x * BLK + wid * 32;   // 32 samples per warp
    float z[4], logp[4];
#pragma unroll
    for (int rs = 0; rs < 4; rs++) {
        int s = gwbase + q + 8 * rs;
        z[rs] = __ldg(T + s);
        logp[rs] = 0.0f;
        const float4* cp = reinterpret_cast<const float4*>(cond) + s * 2;
        float4 ca = __ldg(cp), cb = __ldg(cp + 1);
        float cc[8] = {ca.x, ca.y, ca.z, ca.w, cb.x, cb.y, cb.z, cb.w};
#pragma unroll
        for (int kp = 0; kp < 4; kp++) {
            int kt = kp >> 1, ee = kp & 1;
            int u0 = 16 * kt + 8 * ee + 2 * c4;
            int u1 = u0 + 1;
            float p0 = __ldg(gb1 + u0), p1 = __ldg(gb1 + u1);
#pragma unroll
            for (int c = 0; c < 8; c++) {
                p0 = fmaf(cc[c], __ldg(gW1 + u0 * 9 + 1 + c), p0);
                p1 = fmaf(cc[c], __ldg(gW1 + u1 * 9 + 1 + c), p1);
            }
            spre1[(rs * 4 + kp) * BLK + tid] = make_float2(p0, p1);
        }
    }
    const float b3v = __ldg(gb3);
    __syncthreads();

    const float dt  = 1.0f / (float)NSTEPS;
    const float dt6 = dt / 6.0f;

#pragma unroll 1
    for (int step = 0; step < NSTEPS; step++) {
        float zs[4], az[4], ad4[4];
#pragma unroll
        for (int rs = 0; rs < 4; rs++) { zs[rs] = z[rs]; az[rs] = 0.0f; ad4[rs] = 0.0f; }

#pragma unroll 1
        for (int st = 0; st < 4; st++) {
            float accS[32], accT[32];

            // ---- fused layer1 (f16x2 tanh) + dual f16 matvec over kt ----
#pragma unroll
            for (int kt = 0; kt < 2; kt++) {
                u32 hA[4][2], gA[4][2];   // [rs][e]
#pragma unroll
                for (int ee = 0; ee < 2; ee++) {
                    int kp = 2 * kt + ee;
                    int idx = kp * 4 + c4;
                    float2 wv = swf[idx];
                    u32 w16 = sw16[idx], nw16 = snw16[idx];
#pragma unroll
                    for (int rs = 0; rs < 4; rs++) {
                        float2 pr = spre1[(rs * 4 + kp) * BLK + tid];
                        float x0 = fmaf(zs[rs], wv.x, pr.x);
                        float x1 = fmaf(zs[rs], wv.y, pr.y);
                        u32 h = tanh_h2(cvt_f16x2(x1, x0));
                        u32 hh = hmul2o(h, h);
                        hA[rs][ee] = h;
                        gA[rs][ee] = hfma2o(hh, nw16, w16);  // (1-h^2)*w10
                    }
                }
#pragma unroll
                for (int nt = 0; nt < 4; nt++) {
                    uint2 bb = sB[(kt * 4 + nt) * 32 + ln];
#pragma unroll
                    for (int mt = 0; mt < 2; mt++) {
                        int ba = (mt * 4 + nt) * 4;
                        if (kt == 0) {
                            float2 bv = sb2[nt * 4 + c4];
                            mma_f16_init(accS[ba], accS[ba+1], accS[ba+2], accS[ba+3],
                                         hA[2*mt][0], hA[2*mt+1][0], hA[2*mt][1], hA[2*mt+1][1],
                                         bb.x, bb.y, bv.x, bv.y);
                            mma_f16_init(accT[ba], accT[ba+1], accT[ba+2], accT[ba+3],
                                         gA[2*mt][0], gA[2*mt+1][0], gA[2*mt][1], gA[2*mt+1][1],
                                         bb.x, bb.y, 0.0f, 0.0f);
                        } else {
                            mma_f16_acc(accS[ba], accS[ba+1], accS[ba+2], accS[ba+3],
                                        hA[2*mt][0], hA[2*mt+1][0], hA[2*mt][1], hA[2*mt+1][1],
                                        bb.x, bb.y);
                            mma_f16_acc(accT[ba], accT[ba+1], accT[ba+2], accT[ba+3],
                                        gA[2*mt][0], gA[2*mt+1][0], gA[2*mt][1], gA[2*mt+1][1],
                                        bb.x, bb.y);
                        }
                    }
                }
            }

            // ---- epilogue via MMA: dz = w3.h2 (+b3), dv = w3.(t - h2^2 t) ----
            float kz[4], kd[4];
#pragma unroll
            for (int mt = 0; mt < 2; mt++) {
                u32 he[4], ho[4], ue[4], uo[4];   // [nt], rows rs=2mt / 2mt+1
#pragma unroll
                for (int nt = 0; nt < 4; nt++) {
                    int ba = (mt * 4 + nt) * 4;
                    u32 hp0 = tanh_h2(cvt_f16x2(accS[ba + 1], accS[ba + 0]));
                    u32 hp1 = tanh_h2(cvt_f16x2(accS[ba + 3], accS[ba + 2]));
                    he[nt] = hp0; ho[nt] = hp1;
                    u32 t0 = cvt_f16x2(accT[ba + 1], accT[ba + 0]);
                    u32 t1 = cvt_f16x2(accT[ba + 3], accT[ba + 2]);
                    ue[nt] = hsub2o(t0, hmul2o(hmul2o(hp0, hp0), t0));
                    uo[nt] = hsub2o(t1, hmul2o(hmul2o(hp1, hp1), t1));
                }
                // dz MMAs: A = h2 (rows = samples, k = n-units), B = w3 repl.
                float dz0, dzu1, dz1, dzu3;
                mma_f16_init(dz0, dzu1, dz1, dzu3,
                             he[0], ho[0], he[1], ho[1],
                             w3b0[0], w3b1[0], b3v, b3v);
                mma_f16_acc(dz0, dzu1, dz1, dzu3,
                            he[2], ho[2], he[3], ho[3],
                            w3b0[1], w3b1[1]);
                float dv0, dvu1, dv1, dvu3;
                mma_f16_init(dv0, dvu1, dv1, dvu3,
                             ue[0], uo[0], ue[1], uo[1],
                             w3b0[0], w3b1[0], 0.0f, 0.0f);
                mma_f16_acc(dv0, dvu1, dv1, dvu3,
                            ue[2], uo[2], ue[3], uo[3],
                            w3b0[1], w3b1[1]);
                kz[2*mt] = dz0; kz[2*mt+1] = dz1;   // b3 already included
                kd[2*mt] = dv0; kd[2*mt+1] = dv1;
            }

            // ---- RK accumulate (no shuffles needed) ----
            const float coef = (st == 1 || st == 2) ? 2.0f : 1.0f;
            const float a = (st == 2) ? dt : (0.5f * dt);
#pragma unroll
            for (int rs = 0; rs < 4; rs++) {
                az[rs]  = fmaf(coef, kz[rs], az[rs]);
                ad4[rs] = fmaf(coef, kd[rs], ad4[rs]);
                zs[rs]  = fmaf(a, kz[rs], z[rs]);
            }
        }

#pragma unroll
        for (int rs = 0; rs < 4; rs++) {
            z[rs]    = fmaf(dt6, az[rs],  z[rs]);
            logp[rs] = fmaf(dt6, ad4[rs], logp[rs]);
        }
    }

    if (c4 == 0) {
#pragma unroll
        for (int rs = 0; rs < 4; rs++) {
            int s = gwbase + q + 8 * rs;
            out[s]     = z[rs];
            out[B + s] = logp[rs];
        }
    }
}

extern "C" void kernel_launch(void* const* d_in, const int* in_sizes, int n_in,
                              void* d_out, int out_size) {
    const float* T    = (const float*)d_in[0];
    const float* cond = (const float*)d_in[1];
    const float* W1   = (const float*)d_in[2];
    const float* b1   = (const float*)d_in[3];
    const float* W2   = (const float*)d_in[4];
    const float* b2   = (const float*)d_in[5];
    const float* W3   = (const float*)d_in[6];
    const float* b3   = (const float*)d_in[7];
    float* out = (float*)d_out;

    const int B = in_sizes[0];
    const int blocks = (B + BLK - 1) / BLK;   // 128 samples per CTA (32 per warp)
    cnf_kernel<<<blocks, BLK>>>(T, cond, W1, b1, W2, b2, W3, b3, out, B);
}

// round 16
// speedup vs baseline: 1.0967x; 1.0489x over previous
#include <cuda_runtime.h>
#include <cstdint>

// ConditionalCNF via warp-level mma.sync (m16n8k16 f16, f32 accum).
// R16: layer-1 fully f16 — pre1 stored as f16x2 in smem; x = hfma2(zz,w,pre1)
// feeds tanh.f16x2 directly (removes 2 FFMA + a 20-cyc F2FP from the per-stage
// critical path, and ~30 issue slots/eval). Epilogue dz/dv stay on the tensor
// pipe (R15). 32 samples/warp.
//
//   lane: q = lane>>2, c4 = lane&3
//   sample rows per thread: {q+8rs, rs=0..3}
//   layer-1 k-units per thread: u0 = 16kt+8e+2c4, u0+1  (kt,e in {0,1})
//   D cols per thread: {2c4, 2c4+1} + 8nt

using u32 = unsigned int;

static constexpr int NSTEPS = 20;
static constexpr int BLK = 128;

__device__ __forceinline__ u32 cvt_f16x2(float hi, float lo) {
    u32 d; asm("cvt.rn.f16x2.f32 %0, %1, %2;" : "=r"(d) : "f"(hi), "f"(lo));
    return d;
}
__device__ __forceinline__ u32 tanh_h2(u32 x) {
    u32 d; asm("tanh.approx.f16x2 %0, %1;" : "=r"(d) : "r"(x)); return d;
}
__device__ __forceinline__ u32 hmul2o(u32 a, u32 b) {
    u32 d; asm("mul.rn.f16x2 %0, %1, %2;" : "=r"(d) : "r"(a), "r"(b));
    return d;
}
__device__ __forceinline__ u32 hsub2o(u32 a, u32 b) {
    u32 d; asm("sub.rn.f16x2 %0, %1, %2;" : "=r"(d) : "r"(a), "r"(b));
    return d;
}
__device__ __forceinline__ u32 hfma2o(u32 a, u32 b, u32 c) {
    u32 d; asm("fma.rn.f16x2 %0, %1, %2, %3;" : "=r"(d) : "r"(a), "r"(b), "r"(c));
    return d;
}
__device__ __forceinline__ void mma_f16_acc(float& c0, float& c1, float& c2, float& c3,
                                            u32 a0, u32 a1, u32 a2, u32 a3,
                                            u32 b0, u32 b1) {
    asm volatile("mma.sync.aligned.m16n8k16.row.col.f32.f16.f16.f32 "
                 "{%0,%1,%2,%3}, {%4,%5,%6,%7}, {%8,%9}, {%0,%1,%2,%3};"
                 : "+f"(c0), "+f"(c1), "+f"(c2), "+f"(c3)
                 : "r"(a0), "r"(a1), "r"(a2), "r"(a3), "r"(b0), "r"(b1));
}
__device__ __forceinline__ void mma_f16_init(float& d0, float& d1, float& d2, float& d3,
                                             u32 a0, u32 a1, u32 a2, u32 a3,
                                             u32 b0, u32 b1, float cl, float ch) {
    asm volatile("mma.sync.aligned.m16n8k16.row.col.f32.f16.f16.f32 "
                 "{%0,%1,%2,%3}, {%4,%5,%6,%7}, {%8,%9}, {%10,%11,%10,%11};"
                 : "=f"(d0), "=f"(d1), "=f"(d2), "=f"(d3)
                 : "r"(a0), "r"(a1), "r"(a2), "r"(a3), "r"(b0), "r"(b1),
                   "f"(cl), "f"(ch));
}

__global__ void __launch_bounds__(BLK, 4)
cnf_kernel(const float* __restrict__ T,
           const float* __restrict__ cond,
           const float* __restrict__ gW1,
           const float* __restrict__ gb1,
           const float* __restrict__ gW2,
           const float* __restrict__ gb2,
           const float* __restrict__ gW3,
           const float* __restrict__ gb3,
           float* __restrict__ out,
           int B)
{
    __shared__ u32   spre1h[16 * BLK];  // layer1 preact f16x2 [slot][tid] (8 KB)
    __shared__ uint2 sB    [8 * 32];    // W2 f16x2 B-frags [tile][lane]   (2 KB)
    __shared__ u32   sw16  [16];        // w10 f16x2  [kp*4+c4]
    __shared__ u32   snw16 [16];        // -w10 f16x2
    __shared__ float2 sb2  [16];        // {b2[n0], b2[n0+1]} per (nt,c4)

    const int tid = threadIdx.x;
    const int ln  = tid & 31;
    const int wid = tid >> 5;
    const int q   = ln >> 2;
    const int c4  = ln & 3;

    // ---- one-time smem init ----
    for (int e = tid; e < 8 * 32; e += BLK) {
        int t = e >> 5, l = e & 31;
        int kt = t >> 2, nt = t & 3;
        int n  = (l >> 2) + 8 * nt;
        int k0 = 16 * kt + 2 * (l & 3);
        const float* r = gW2 + n * 32 + k0;
        sB[e] = make_uint2(cvt_f16x2(r[1], r[0]), cvt_f16x2(r[9], r[8]));
    }
    if (tid < 16) {
        int kp = tid >> 2, cc = tid & 3;     // kp = 2*kt + e
        int kt = kp >> 1, ee = kp & 1;
        int u0 = 16 * kt + 8 * ee + 2 * cc;
        float w0 = gW1[u0 * 9], w1 = gW1[(u0 + 1) * 9];
        sw16[tid]  = cvt_f16x2(w1, w0);
        snw16[tid] = cvt_f16x2(-w1, -w0);
        int nt = tid >> 2;
        int n0 = 2 * cc + 8 * nt;
        sb2[tid] = make_float2(gb2[n0], gb2[n0 + 1]);
    }

    // w3 B-fragments for the epilogue MMAs (replicated over n; per-thread regs)
    u32 w3b0[2], w3b1[2];
#pragma unroll
    for (int kh = 0; kh < 2; kh++) {
        int k0 = 16 * kh + 2 * c4;
        w3b0[kh] = cvt_f16x2(__ldg(gW3 + k0 + 1), __ldg(gW3 + k0));
        w3b1[kh] = cvt_f16x2(__ldg(gW3 + k0 + 9), __ldg(gW3 + k0 + 8));
    }

    // ---- per-thread setup: RK state + pre1 (f16x2) into smem ----
    const int gwbase = blockIdx.x * BLK + wid * 32;   // 32 samples per warp
    float z[4], logp[4];
#pragma unroll
    for (int rs = 0; rs < 4; rs++) {
        int s = gwbase + q + 8 * rs;
        z[rs] = __ldg(T + s);
        logp[rs] = 0.0f;
        const float4* cp = reinterpret_cast<const float4*>(cond) + s * 2;
        float4 ca = __ldg(cp), cb = __ldg(cp + 1);
        float cc[8] = {ca.x, ca.y, ca.z, ca.w, cb.x, cb.y, cb.z, cb.w};
#pragma unroll
        for (int kp = 0; kp < 4; kp++) {
            int kt = kp >> 1, ee = kp & 1;
            int u0 = 16 * kt + 8 * ee + 2 * c4;
            int u1 = u0 + 1;
            float p0 = __ldg(gb1 + u0), p1 = __ldg(gb1 + u1);
#pragma unroll
            for (int c = 0; c < 8; c++) {
                p0 = fmaf(cc[c], __ldg(gW1 + u0 * 9 + 1 + c), p0);
                p1 = fmaf(cc[c], __ldg(gW1 + u1 * 9 + 1 + c), p1);
            }
            spre1h[(rs * 4 + kp) * BLK + tid] = cvt_f16x2(p1, p0);
        }
    }
    const float b3v = __ldg(gb3);
    __syncthreads();

    const float dt  = 1.0f / (float)NSTEPS;
    const float dt6 = dt / 6.0f;

#pragma unroll 1
    for (int step = 0; step < NSTEPS; step++) {
        float zs[4], az[4], ad4[4];
#pragma unroll
        for (int rs = 0; rs < 4; rs++) { zs[rs] = z[rs]; az[rs] = 0.0f; ad4[rs] = 0.0f; }

#pragma unroll 1
        for (int st = 0; st < 4; st++) {
            float accS[32], accT[32];

            u32 zz[4];
#pragma unroll
            for (int rs = 0; rs < 4; rs++) zz[rs] = cvt_f16x2(zs[rs], zs[rs]);

            // ---- fused f16 layer1 + dual f16 matvec over kt ----
#pragma unroll
            for (int kt = 0; kt < 2; kt++) {
                u32 hA[4][2], gA[4][2];   // [rs][e]
#pragma unroll
                for (int ee = 0; ee < 2; ee++) {
                    int kp = 2 * kt + ee;
                    int idx = kp * 4 + c4;
                    u32 w16 = sw16[idx], nw16 = snw16[idx];
#pragma unroll
                    for (int rs = 0; rs < 4; rs++) {
                        u32 x = hfma2o(zz[rs], w16, spre1h[(rs * 4 + kp) * BLK + tid]);
                        u32 h = tanh_h2(x);
                        u32 hh = hmul2o(h, h);
                        hA[rs][ee] = h;
                        gA[rs][ee] = hfma2o(hh, nw16, w16);  // (1-h^2)*w10
                    }
                }
#pragma unroll
                for (int nt = 0; nt < 4; nt++) {
                    uint2 bb = sB[(kt * 4 + nt) * 32 + ln];
#pragma unroll
                    for (int mt = 0; mt < 2; mt++) {
                        int ba = (mt * 4 + nt) * 4;
                        if (kt == 0) {
                            float2 bv = sb2[nt * 4 + c4];
                            mma_f16_init(accS[ba], accS[ba+1], accS[ba+2], accS[ba+3],
                                         hA[2*mt][0], hA[2*mt+1][0], hA[2*mt][1], hA[2*mt+1][1],
                                         bb.x, bb.y, bv.x, bv.y);
                            mma_f16_init(accT[ba], accT[ba+1], accT[ba+2], accT[ba+3],
                                         gA[2*mt][0], gA[2*mt+1][0], gA[2*mt][1], gA[2*mt+1][1],
                                         bb.x, bb.y, 0.0f, 0.0f);
                        } else {
                            mma_f16_acc(accS[ba], accS[ba+1], accS[ba+2], accS[ba+3],
                                        hA[2*mt][0], hA[2*mt+1][0], hA[2*mt][1], hA[2*mt+1][1],
                                        bb.x, bb.y);
                            mma_f16_acc(accT[ba], accT[ba+1], accT[ba+2], accT[ba+3],
                                        gA[2*mt][0], gA[2*mt+1][0], gA[2*mt][1], gA[2*mt+1][1],
                                        bb.x, bb.y);
                        }
                    }
                }
            }

            // ---- epilogue via MMA: dz = w3.h2 (+b3), dv = w3.(t - h2^2 t) ----
            float kz[4], kd[4];
#pragma unroll
            for (int mt = 0; mt < 2; mt++) {
                u32 he[4], ho[4], ue[4], uo[4];   // [nt], rows rs=2mt / 2mt+1
#pragma unroll
                for (int nt = 0; nt < 4; nt++) {
                    int ba = (mt * 4 + nt) * 4;
                    u32 hp0 = tanh_h2(cvt_f16x2(accS[ba + 1], accS[ba + 0]));
                    u32 hp1 = tanh_h2(cvt_f16x2(accS[ba + 3], accS[ba + 2]));
                    he[nt] = hp0; ho[nt] = hp1;
                    u32 t0 = cvt_f16x2(accT[ba + 1], accT[ba + 0]);
                    u32 t1 = cvt_f16x2(accT[ba + 3], accT[ba + 2]);
                    ue[nt] = hsub2o(t0, hmul2o(hmul2o(hp0, hp0), t0));
                    uo[nt] = hsub2o(t1, hmul2o(hmul2o(hp1, hp1), t1));
                }
                float dz0, dzu1, dz1, dzu3;
                mma_f16_init(dz0, dzu1, dz1, dzu3,
                             he[0], ho[0], he[1], ho[1],
                             w3b0[0], w3b1[0], b3v, b3v);
                mma_f16_acc(dz0, dzu1, dz1, dzu3,
                            he[2], ho[2], he[3], ho[3],
                            w3b0[1], w3b1[1]);
                float dv0, dvu1, dv1, dvu3;
                mma_f16_init(dv0, dvu1, dv1, dvu3,
                             ue[0], uo[0], ue[1], uo[1],
                             w3b0[0], w3b1[0], 0.0f, 0.0f);
                mma_f16_acc(dv0, dvu1, dv1, dvu3,
                            ue[2], uo[2], ue[3], uo[3],
                            w3b0[1], w3b1[1]);
                kz[2*mt] = dz0; kz[2*mt+1] = dz1;   // b3 already included
                kd[2*mt] = dv0; kd[2*mt+1] = dv1;
            }

            // ---- RK accumulate ----
            const float coef = (st == 1 || st == 2) ? 2.0f : 1.0f;
            const float a = (st == 2) ? dt : (0.5f * dt);
#pragma unroll
            for (int rs = 0; rs < 4; rs++) {
                az[rs]  = fmaf(coef, kz[rs], az[rs]);
                ad4[rs] = fmaf(coef, kd[rs], ad4[rs]);
                zs[rs]  = fmaf(a, kz[rs], z[rs]);
            }
        }

#pragma unroll
        for (int rs = 0; rs < 4; rs++) {
            z[rs]    = fmaf(dt6, az[rs],  z[rs]);
            logp[rs] = fmaf(dt6, ad4[rs], logp[rs]);
        }
    }

    if (c4 == 0) {
#pragma unroll
        for (int rs = 0; rs < 4; rs++) {
            int s = gwbase + q + 8 * rs;
            out[s]     = z[rs];
            out[B + s] = logp[rs];
        }
    }
}

extern "C" void kernel_launch(void* const* d_in, const int* in_sizes, int n_in,
                              void* d_out, int out_size) {
    const float* T    = (const float*)d_in[0];
    const float* cond = (const float*)d_in[1];
    const float* W1   = (const float*)d_in[2];
    const float* b1   = (const float*)d_in[3];
    const float* W2   = (const float*)d_in[4];
    const float* b2   = (const float*)d_in[5];
    const float* W3   = (const float*)d_in[6];
    const float* b3   = (const float*)d_in[7];
    float* out = (float*)d_out;

    const int B = in_sizes[0];
    const int blocks = (B + BLK - 1) / BLK;   // 128 samples per CTA (32 per warp)
    cnf_kernel<<<blocks, BLK>>>(T, cond, W1, b1, W2, b2, W3, b3, out, B);
}

// round 17
// speedup vs baseline: 1.2718x; 1.1596x over previous
#include <cuda_runtime.h>
#include <cstdint>

// ConditionalCNF via warp-level mma.sync.
// R17: S/T matvecs switch to f16-accumulate HMMA (m16n8k16.f16.f16.f16.f16).
// D frags are f16x2 col-pairs == tanh.approx.f16x2 / u-prep operands: all 32
// epilogue F2FP cvts disappear (ALU + 2x20cyc chain latency), accumulator
// regs halve (64->32) -> 5 CTAs/SM. Epilogue dz/dv MMAs keep f32 accum (they
// feed the 80-step RK recurrence). 32 samples/warp.
//
//   lane: q = lane>>2, c4 = lane&3
//   sample rows per thread: {q+8rs, rs=0..3}
//   layer-1 k-units per thread: u0 = 16kt+8e+2c4, u0+1  (kt,e in {0,1})
//   D cols per thread: {2c4, 2c4+1} + 8nt

using u32 = unsigned int;

static constexpr int NSTEPS = 20;
static constexpr int BLK = 128;

__device__ __forceinline__ u32 cvt_f16x2(float hi, float lo) {
    u32 d; asm("cvt.rn.f16x2.f32 %0, %1, %2;" : "=r"(d) : "f"(hi), "f"(lo));
    return d;
}
__device__ __forceinline__ u32 tanh_h2(u32 x) {
    u32 d; asm("tanh.approx.f16x2 %0, %1;" : "=r"(d) : "r"(x)); return d;
}
__device__ __forceinline__ u32 hmul2o(u32 a, u32 b) {
    u32 d; asm("mul.rn.f16x2 %0, %1, %2;" : "=r"(d) : "r"(a), "r"(b));
    return d;
}
__device__ __forceinline__ u32 hsub2o(u32 a, u32 b) {
    u32 d; asm("sub.rn.f16x2 %0, %1, %2;" : "=r"(d) : "r"(a), "r"(b));
    return d;
}
__device__ __forceinline__ u32 hfma2o(u32 a, u32 b, u32 c) {
    u32 d; asm("fma.rn.f16x2 %0, %1, %2, %3;" : "=r"(d) : "r"(a), "r"(b), "r"(c));
    return d;
}
// f16-accumulate HMMA: D,C are 2 regs of f16x2 (col pairs; reg0=row q, reg1=row q+8)
__device__ __forceinline__ void mma_h16_acc(u32& d0, u32& d1,
                                            u32 a0, u32 a1, u32 a2, u32 a3,
                                            u32 b0, u32 b1) {
    asm volatile("mma.sync.aligned.m16n8k16.row.col.f16.f16.f16.f16 "
                 "{%0,%1}, {%2,%3,%4,%5}, {%6,%7}, {%0,%1};"
                 : "+r"(d0), "+r"(d1)
                 : "r"(a0), "r"(a1), "r"(a2), "r"(a3), "r"(b0), "r"(b1));
}
__device__ __forceinline__ void mma_h16_init(u32& d0, u32& d1,
                                             u32 a0, u32 a1, u32 a2, u32 a3,
                                             u32 b0, u32 b1, u32 cc) {
    asm volatile("mma.sync.aligned.m16n8k16.row.col.f16.f16.f16.f16 "
                 "{%0,%1}, {%2,%3,%4,%5}, {%6,%7}, {%8,%8};"
                 : "=r"(d0), "=r"(d1)
                 : "r"(a0), "r"(a1), "r"(a2), "r"(a3), "r"(b0), "r"(b1), "r"(cc));
}
// f32-accumulate for the epilogue reductions
__device__ __forceinline__ void mma_f16_acc(float& c0, float& c1, float& c2, float& c3,
                                            u32 a0, u32 a1, u32 a2, u32 a3,
                                            u32 b0, u32 b1) {
    asm volatile("mma.sync.aligned.m16n8k16.row.col.f32.f16.f16.f32 "
                 "{%0,%1,%2,%3}, {%4,%5,%6,%7}, {%8,%9}, {%0,%1,%2,%3};"
                 : "+f"(c0), "+f"(c1), "+f"(c2), "+f"(c3)
                 : "r"(a0), "r"(a1), "r"(a2), "r"(a3), "r"(b0), "r"(b1));
}
__device__ __forceinline__ void mma_f16_init(float& d0, float& d1, float& d2, float& d3,
                                             u32 a0, u32 a1, u32 a2, u32 a3,
                                             u32 b0, u32 b1, float cl, float ch) {
    asm volatile("mma.sync.aligned.m16n8k16.row.col.f32.f16.f16.f32 "
                 "{%0,%1,%2,%3}, {%4,%5,%6,%7}, {%8,%9}, {%10,%11,%10,%11};"
                 : "=f"(d0), "=f"(d1), "=f"(d2), "=f"(d3)
                 : "r"(a0), "r"(a1), "r"(a2), "r"(a3), "r"(b0), "r"(b1),
                   "f"(cl), "f"(ch));
}

__global__ void __launch_bounds__(BLK, 5)
cnf_kernel(const float* __restrict__ T,
           const float* __restrict__ cond,
           const float* __restrict__ gW1,
           const float* __restrict__ gb1,
           const float* __restrict__ gW2,
           const float* __restrict__ gb2,
           const float* __restrict__ gW3,
           const float* __restrict__ gb3,
           float* __restrict__ out,
           int B)
{
    __shared__ u32   spre1h[16 * BLK];  // layer1 preact f16x2 [slot][tid] (8 KB)
    __shared__ uint2 sB    [8 * 32];    // W2 f16x2 B-frags [tile][lane]   (2 KB)
    __shared__ u32   sw16  [16];        // w10 f16x2  [kp*4+c4]
    __shared__ u32   snw16 [16];        // -w10 f16x2
    __shared__ u32   sb2h  [16];        // {b2[n0], b2[n0+1]} f16x2 per (nt,c4)

    const int tid = threadIdx.x;
    const int ln  = tid & 31;
    const int wid = tid >> 5;
    const int q   = ln >> 2;
    const int c4  = ln & 3;

    // ---- one-time smem init ----
    for (int e = tid; e < 8 * 32; e += BLK) {
        int t = e >> 5, l = e & 31;
        int kt = t >> 2, nt = t & 3;
        int n  = (l >> 2) + 8 * nt;
        int k0 = 16 * kt + 2 * (l & 3);
        const float* r = gW2 + n * 32 + k0;
        sB[e] = make_uint2(cvt_f16x2(r[1], r[0]), cvt_f16x2(r[9], r[8]));
    }
    if (tid < 16) {
        int kp = tid >> 2, cc = tid & 3;     // kp = 2*kt + e
        int kt = kp >> 1, ee = kp & 1;
        int u0 = 16 * kt + 8 * ee + 2 * cc;
        float w0 = gW1[u0 * 9], w1 = gW1[(u0 + 1) * 9];
        sw16[tid]  = cvt_f16x2(w1, w0);
        snw16[tid] = cvt_f16x2(-w1, -w0);
        int nt = tid >> 2;
        int n0 = 2 * cc + 8 * nt;
        sb2h[tid] = cvt_f16x2(gb2[n0 + 1], gb2[n0]);
    }

    // w3 B-fragments for the epilogue MMAs (replicated over n; per-thread regs)
    u32 w3b0[2], w3b1[2];
#pragma unroll
    for (int kh = 0; kh < 2; kh++) {
        int k0 = 16 * kh + 2 * c4;
        w3b0[kh] = cvt_f16x2(__ldg(gW3 + k0 + 1), __ldg(gW3 + k0));
        w3b1[kh] = cvt_f16x2(__ldg(gW3 + k0 + 9), __ldg(gW3 + k0 + 8));
    }

    // ---- per-thread setup: RK state + pre1 (f16x2) into smem ----
    const int gwbase = blockIdx.x * BLK + wid * 32;   // 32 samples per warp
    float z[4], logp[4];
#pragma unroll
    for (int rs = 0; rs < 4; rs++) {
        int s = gwbase + q + 8 * rs;
        z[rs] = __ldg(T + s);
        logp[rs] = 0.0f;
        const float4* cp = reinterpret_cast<const float4*>(cond) + s * 2;
        float4 ca = __ldg(cp), cb = __ldg(cp + 1);
        float cc[8] = {ca.x, ca.y, ca.z, ca.w, cb.x, cb.y, cb.z, cb.w};
#pragma unroll
        for (int kp = 0; kp < 4; kp++) {
            int kt = kp >> 1, ee = kp & 1;
            int u0 = 16 * kt + 8 * ee + 2 * c4;
            int u1 = u0 + 1;
            float p0 = __ldg(gb1 + u0), p1 = __ldg(gb1 + u1);
#pragma unroll
            for (int c = 0; c < 8; c++) {
                p0 = fmaf(cc[c], __ldg(gW1 + u0 * 9 + 1 + c), p0);
                p1 = fmaf(cc[c], __ldg(gW1 + u1 * 9 + 1 + c), p1);
            }
            spre1h[(rs * 4 + kp) * BLK + tid] = cvt_f16x2(p1, p0);
        }
    }
    const float b3v = __ldg(gb3);
    __syncthreads();

    const float dt  = 1.0f / (float)NSTEPS;
    const float dt6 = dt / 6.0f;

#pragma unroll 1
    for (int step = 0; step < NSTEPS; step++) {
        float zs[4], az[4], ad4[4];
#pragma unroll
        for (int rs = 0; rs < 4; rs++) { zs[rs] = z[rs]; az[rs] = 0.0f; ad4[rs] = 0.0f; }

#pragma unroll 1
        for (int st = 0; st < 4; st++) {
            // f16x2 accumulators: [ (mt*4+nt)*2 + {row q, row q+8} ]
            u32 accS[16], accT[16];

            u32 zz[4];
#pragma unroll
            for (int rs = 0; rs < 4; rs++) zz[rs] = cvt_f16x2(zs[rs], zs[rs]);

            // ---- fused f16 layer1 + dual f16 matvec over kt ----
#pragma unroll
            for (int kt = 0; kt < 2; kt++) {
                u32 hA[4][2], gA[4][2];   // [rs][e]
#pragma unroll
                for (int ee = 0; ee < 2; ee++) {
                    int kp = 2 * kt + ee;
                    int idx = kp * 4 + c4;
                    u32 w16 = sw16[idx], nw16 = snw16[idx];
#pragma unroll
                    for (int rs = 0; rs < 4; rs++) {
                        u32 x = hfma2o(zz[rs], w16, spre1h[(rs * 4 + kp) * BLK + tid]);
                        u32 h = tanh_h2(x);
                        u32 hh = hmul2o(h, h);
                        hA[rs][ee] = h;
                        gA[rs][ee] = hfma2o(hh, nw16, w16);  // (1-h^2)*w10
                    }
                }
#pragma unroll
                for (int nt = 0; nt < 4; nt++) {
                    uint2 bb = sB[(kt * 4 + nt) * 32 + ln];
#pragma unroll
                    for (int mt = 0; mt < 2; mt++) {
                        int ba = (mt * 4 + nt) * 2;
                        if (kt == 0) {
                            mma_h16_init(accS[ba], accS[ba+1],
                                         hA[2*mt][0], hA[2*mt+1][0], hA[2*mt][1], hA[2*mt+1][1],
                                         bb.x, bb.y, sb2h[nt * 4 + c4]);
                            mma_h16_init(accT[ba], accT[ba+1],
                                         gA[2*mt][0], gA[2*mt+1][0], gA[2*mt][1], gA[2*mt+1][1],
                                         bb.x, bb.y, 0u);
                        } else {
                            mma_h16_acc(accS[ba], accS[ba+1],
                                        hA[2*mt][0], hA[2*mt+1][0], hA[2*mt][1], hA[2*mt+1][1],
                                        bb.x, bb.y);
                            mma_h16_acc(accT[ba], accT[ba+1],
                                        gA[2*mt][0], gA[2*mt+1][0], gA[2*mt][1], gA[2*mt+1][1],
                                        bb.x, bb.y);
                        }
                    }
                }
            }

            // ---- epilogue via MMA: dz = w3.h2 (+b3), dv = w3.(t - h2^2 t) ----
            float kz[4], kd[4];
#pragma unroll
            for (int mt = 0; mt < 2; mt++) {
                u32 he[4], ho[4], ue[4], uo[4];   // [nt], rows rs=2mt / 2mt+1
#pragma unroll
                for (int nt = 0; nt < 4; nt++) {
                    int ba = (mt * 4 + nt) * 2;
                    u32 hp0 = tanh_h2(accS[ba]);        // direct: no cvt
                    u32 hp1 = tanh_h2(accS[ba + 1]);
                    he[nt] = hp0; ho[nt] = hp1;
                    u32 t0 = accT[ba], t1 = accT[ba + 1];
                    ue[nt] = hsub2o(t0, hmul2o(hmul2o(hp0, hp0), t0));
                    uo[nt] = hsub2o(t1, hmul2o(hmul2o(hp1, hp1), t1));
                }
                float dz0, dzu1, dz1, dzu3;
                mma_f16_init(dz0, dzu1, dz1, dzu3,
                             he[0], ho[0], he[1], ho[1],
                             w3b0[0], w3b1[0], b3v, b3v);
                mma_f16_acc(dz0, dzu1, dz1, dzu3,
                            he[2], ho[2], he[3], ho[3],
                            w3b0[1], w3b1[1]);
                float dv0, dvu1, dv1, dvu3;
                mma_f16_init(dv0, dvu1, dv1, dvu3,
                             ue[0], uo[0], ue[1], uo[1],
                             w3b0[0], w3b1[0], 0.0f, 0.0f);
                mma_f16_acc(dv0, dvu1, dv1, dvu3,
                            ue[2], uo[2], ue[3], uo[3],
                            w3b0[1], w3b1[1]);
                kz[2*mt] = dz0; kz[2*mt+1] = dz1;   // b3 already included
                kd[2*mt] = dv0; kd[2*mt+1] = dv1;
            }

            // ---- RK accumulate ----
            const float coef = (st == 1 || st == 2) ? 2.0f : 1.0f;
            const float a = (st == 2) ? dt : (0.5f * dt);
#pragma unroll
            for (int rs = 0; rs < 4; rs++) {
                az[rs]  = fmaf(coef, kz[rs], az[rs]);
                ad4[rs] = fmaf(coef, kd[rs], ad4[rs]);
                zs[rs]  = fmaf(a, kz[rs], z[rs]);
            }
        }

#pragma unroll
        for (int rs = 0; rs < 4; rs++) {
            z[rs]    = fmaf(dt6, az[rs],  z[rs]);
            logp[rs] = fmaf(dt6, ad4[rs], logp[rs]);
        }
    }

    if (c4 == 0) {
#pragma unroll
        for (int rs = 0; rs < 4; rs++) {
            int s = gwbase + q + 8 * rs;
            out[s]     = z[rs];
            out[B + s] = logp[rs];
        }
    }
}

extern "C" void kernel_launch(void* const* d_in, const int* in_sizes, int n_in,
                              void* d_out, int out_size) {
    const float* T    = (const float*)d_in[0];
    const float* cond = (const float*)d_in[1];
    const float* W1   = (const float*)d_in[2];
    const float* b1   = (const float*)d_in[3];
    const float* W2   = (const float*)d_in[4];
    const float* b2   = (const float*)d_in[5];
    const float* W3   = (const float*)d_in[6];
    const float* b3   = (const float*)d_in[7];
    float* out = (float*)d_out;

    const int B = in_sizes[0];
    const int blocks = (B + BLK - 1) / BLK;   // 128 samples per CTA (32 per warp)
    cnf_kernel<<<blocks, BLK>>>(T, cond, W1, b1, W2, b2, W3, b3, out, B);
}